// round 11
// baseline (speedup 1.0000x reference)
#include <cuda_runtime.h>
#include <cuda_fp16.h>
#include <math.h>
#include <stdint.h>

// T=4, B=8, N=1024, C=512, NH=8, D=64, TB=32, M=TB*N=32768
#define MM 32768
#define O3 1536
#define CC 512
#define FLAG_CAP (1 << 21)
#define TAU 4e-3f

// ---------------- scratch (static __device__, no allocation) ----------------
__device__ float g_Y [(size_t)O3 * MM];   // qkv pre-activations (exact) [o][m]
__device__ float g_S [(size_t)O3 * MM];   // qkv spikes (exact)
__device__ float g_KV[256 * 64 * 64];
__device__ float g_A [(size_t)CC * MM];   // attention pre-LIF (exact)
__device__ float g_Sa[(size_t)CC * MM];   // attention spikes (exact)
__device__ float g_P [(size_t)CC * MM];   // proj pre-act (TC approx)
__device__ float g_scale [O3], g_shift [O3];
__device__ float g_scale2[CC], g_shift2[CC];
__device__ double g_part[2048][8][2];
__device__ int g_cnt2;
__device__ int g_list2[FLAG_CAP];

// fp16 tile blobs: chunk = 128 rows x 32 k halves = 8KB, plain row-major (64B rows)
__device__ __half g_Ph[(size_t)4   * 48 * 4096]; // proj W 3-splits (x 2^13) [ob][48]
__device__ __half g_Sh[(size_t)256 * 16 * 4096]; // attn spikes (exact fp16) [mb][16]

#define UNSCALEP 1.220703125e-4f          // 2^-13

// ---------------- PTX helpers -------------------------------------------------
__device__ __forceinline__ uint32_t smem_u32(const void* p) {
    uint32_t a;
    asm("{ .reg .u64 t; cvta.to.shared.u64 t, %1; cvt.u32.u64 %0, t; }" : "=r"(a) : "l"(p));
    return a;
}
#define LDSM4(r, addr) \
    asm volatile("ldmatrix.sync.aligned.m8n8.x4.shared.b16 {%0,%1,%2,%3}, [%4];" \
        : "=r"((r)[0]), "=r"((r)[1]), "=r"((r)[2]), "=r"((r)[3]) : "r"(addr))
#define MMA16816(d, a, b0, b1) \
    asm volatile("mma.sync.aligned.m16n8k16.row.col.f32.f16.f16.f32 " \
        "{%0,%1,%2,%3},{%4,%5,%6,%7},{%8,%9},{%0,%1,%2,%3};" \
        : "+f"((d)[0]), "+f"((d)[1]), "+f"((d)[2]), "+f"((d)[3]) \
        : "r"((a)[0]), "r"((a)[1]), "r"((a)[2]), "r"((a)[3]), "r"(b0), "r"(b1))

__device__ __forceinline__ unsigned long long pack4h(__half a, __half b, __half c, __half d) {
    return (unsigned long long)__half_as_ushort(a)
         | ((unsigned long long)__half_as_ushort(b) << 16)
         | ((unsigned long long)__half_as_ushort(c) << 32)
         | ((unsigned long long)__half_as_ushort(d) << 48);
}
__device__ __forceinline__ void split3s(float f, float scale,
                                        __half& h0, __half& h1, __half& h2) {
    float fs = f * scale;
    h0 = __float2half_rn(fs);
    float r1 = fs - __half2float(h0);
    h1 = __float2half_rn(r1);
    float r2 = r1 - __half2float(h1);
    h2 = __float2half_rn(r2);
}

__global__ void zero_counters() { g_cnt2 = 0; }

// ---------------- GEMM1: exact scalar (R9 bit-proven) ------------------------
__global__ __launch_bounds__(256) void gemm_qkv(
    const float* __restrict__ Wq, const float* __restrict__ Wk,
    const float* __restrict__ Wv, const float* __restrict__ X)
{
    __shared__ float As[16][132];
    __shared__ float Bs[16][132];
    int m0 = blockIdx.x * 128;
    int o0 = blockIdx.y * 128;
    const float* W = Wq; int ob = o0;
    if (o0 >= 1024)      { W = Wv; ob = o0 - 1024; }
    else if (o0 >= 512)  { W = Wk; ob = o0 - 512;  }

    int tid = threadIdx.x;
    int tx = tid & 15, ty = tid >> 4;
    int lr = tid >> 2;
    int lk = (tid & 3) << 2;

    float acc[8][8];
#pragma unroll
    for (int i = 0; i < 8; i++)
#pragma unroll
        for (int j = 0; j < 8; j++) acc[i][j] = 0.f;

    for (int k0 = 0; k0 < 512; k0 += 16) {
#pragma unroll
        for (int rr = 0; rr < 2; rr++) {
            int r = lr + rr * 64;
            float4 a = *(const float4*)&W[(size_t)(ob + r) * 512 + k0 + lk];
            As[lk+0][r] = a.x; As[lk+1][r] = a.y; As[lk+2][r] = a.z; As[lk+3][r] = a.w;
            float4 b = *(const float4*)&X[(size_t)(m0 + r) * 512 + k0 + lk];
            Bs[lk+0][r] = b.x; Bs[lk+1][r] = b.y; Bs[lk+2][r] = b.z; Bs[lk+3][r] = b.w;
        }
        __syncthreads();
#pragma unroll
        for (int kk = 0; kk < 16; kk++) {
            float ar[8], br[8];
            *(float4*)&ar[0] = *(const float4*)&As[kk][ty*8];
            *(float4*)&ar[4] = *(const float4*)&As[kk][ty*8+4];
            *(float4*)&br[0] = *(const float4*)&Bs[kk][tx*8];
            *(float4*)&br[4] = *(const float4*)&Bs[kk][tx*8+4];
#pragma unroll
            for (int i = 0; i < 8; i++)
#pragma unroll
                for (int j = 0; j < 8; j++)
                    acc[i][j] = fmaf(ar[i], br[j], acc[i][j]);
        }
        __syncthreads();
    }
#pragma unroll
    for (int i = 0; i < 8; i++) {
        size_t row = (size_t)(o0 + ty*8 + i) * MM + m0 + tx*8;
        *(float4*)&g_Y[row]   = make_float4(acc[i][0], acc[i][1], acc[i][2], acc[i][3]);
        *(float4*)&g_Y[row+4] = make_float4(acc[i][4], acc[i][5], acc[i][6], acc[i][7]);
    }
}

// ---------------- prep proj W: 3 scaled fp16 splits --------------------------
__global__ __launch_bounds__(256) void prep_w_proj(const float* __restrict__ pw)
{
    int rb = blockIdx.x;                 // 4 blocks x 128 rows
    const float* src = pw + (size_t)rb * 128 * 512;
    int w = threadIdx.x >> 5, lane = threadIdx.x & 31;
    char* base = (char*)g_Ph + (size_t)rb * 48 * 8192;
#pragma unroll 1
    for (int i = 0; i < 16; i++) {
        int r = w + 8 * i;
#pragma unroll
        for (int pass = 0; pass < 4; pass++) {
            int k = pass * 128 + lane * 4;
            float4 v = *(const float4*)&src[(size_t)r * 512 + k];
            __half a0,a1,a2, b0,b1,b2, c0,c1,c2, d0,d1,d2;
            split3s(v.x, 8192.0f, a0, a1, a2);
            split3s(v.y, 8192.0f, b0, b1, b2);
            split3s(v.z, 8192.0f, c0, c1, c2);
            split3s(v.w, 8192.0f, d0, d1, d2);
            int kc = k >> 5;
            uint32_t off = (uint32_t)r * 64 + (k & 31) * 2;
            *(unsigned long long*)(base + (size_t)kc * 8192 + off)        = pack4h(a0, b0, c0, d0);
            *(unsigned long long*)(base + (size_t)(16 + kc) * 8192 + off) = pack4h(a1, b1, c1, d1);
            *(unsigned long long*)(base + (size_t)(32 + kc) * 8192 + off) = pack4h(a2, b2, c2, d2);
        }
    }
}

// transpose-pack attn spikes [c][m] fp32 -> fp16 chunks [mb][16] (128m x 32c)
__global__ __launch_bounds__(128) void pack_spike()
{
    __shared__ __half sm[128][72];
    int mb = blockIdx.x, kc = blockIdx.y, t = threadIdx.x;
    const __half one  = __ushort_as_half(0x3C00);
    const __half zero = __ushort_as_half(0);
#pragma unroll 4
    for (int c = 0; c < 64; c++) {
        float v = g_Sa[(size_t)(kc * 64 + c) * MM + (size_t)mb * 128 + t];
        sm[t][c] = (v != 0.f) ? one : zero;
    }
    __syncthreads();
    char* dst = (char*)g_Sh + ((size_t)mb * 16 + (size_t)kc * 2) * 8192;
#pragma unroll
    for (int i = 0; i < 8; i++) {
        int r = (t >> 3) + i * 16;
        int u = t & 7;
        uint4 val = *(const uint4*)&sm[r][u * 8];
        *(uint4*)(dst + (size_t)(u >> 2) * 8192 + (uint32_t)r * 64 + (u & 3) * 16) = val;
    }
}

// ---------------- TC proj GEMM: g_P[o][m] = sum over 3 W-splits --------------
// CTA 128m x 128o, 8 warps. Slots: 0 = spikes, 1..3 = W splits.
__global__ __launch_bounds__(256) void gemm_proj_tc()
{
    __shared__ __align__(16) char sbuf[40960];
    uint32_t sb = smem_u32(sbuf);
    int tid = threadIdx.x, lane = tid & 31, w = tid >> 5;
    int wm = w & 3, wo = w >> 2;
    int ob = blockIdx.x, mb = blockIdx.y;

    float acc[2][8][4];
#pragma unroll
    for (int i = 0; i < 2; i++)
#pragma unroll
        for (int j = 0; j < 8; j++)
#pragma unroll
            for (int r = 0; r < 4; r++) acc[i][j][r] = 0.f;

    int aL = (wm * 32 + (lane & 7) + ((lane >> 3) & 1) * 8) * 80 + ((lane >> 4) & 1) * 16;
    int bL = (wo * 64 + (lane & 7) + ((lane >> 4) & 1) * 8) * 80 + ((lane >> 3) & 1) * 16;

#pragma unroll 1
    for (int g = 0; g < 16; g++) {
        __syncthreads();
#pragma unroll
        for (int ti = 0; ti < 4; ti++) {
            const char* src = (ti == 0)
                ? (const char*)g_Sh + ((size_t)mb * 16 + g) * 8192
                : (const char*)g_Ph + ((size_t)ob * 48 + (ti - 1) * 16 + g) * 8192;
            char* dst = sbuf + ti * 10240;
#pragma unroll
            for (int j = 0; j < 2; j++) {
                int c = tid + j * 256;
                *(float4*)(dst + (c >> 2) * 80 + (c & 3) * 16) =
                    *(const float4*)(src + (size_t)c * 16);
            }
        }
        __syncthreads();
        uint32_t As = sb + aL;
#pragma unroll
        for (int bi = 0; bi < 3; bi++) {
            uint32_t Bs = sb + (1 + bi) * 10240 + bL;
#pragma unroll
            for (int ks = 0; ks < 2; ks++) {
                uint32_t af[2][4];
                LDSM4(af[0], As + ks * 32);
                LDSM4(af[1], As + 16 * 80 + ks * 32);
                uint32_t bf[4][4];
#pragma unroll
                for (int p = 0; p < 4; p++)
                    LDSM4(bf[p], Bs + p * 16 * 80 + ks * 32);
#pragma unroll
                for (int mt = 0; mt < 2; mt++)
#pragma unroll
                    for (int p = 0; p < 4; p++) {
                        MMA16816(acc[mt][2 * p],     af[mt], bf[p][0], bf[p][1]);
                        MMA16816(acc[mt][2 * p + 1], af[mt], bf[p][2], bf[p][3]);
                    }
            }
        }
    }

    int m0 = mb * 128 + wm * 32 + (lane >> 2);
    int o0 = ob * 128 + wo * 64 + (lane & 3) * 2;
#pragma unroll
    for (int mt = 0; mt < 2; mt++)
#pragma unroll
        for (int nt = 0; nt < 8; nt++)
#pragma unroll
            for (int r = 0; r < 4; r++) {
                int m = m0 + mt * 16 + (r >> 1) * 8;
                int o = o0 + nt * 8 + (r & 1);
                g_P[(size_t)o * MM + m] = acc[mt][nt][r] * UNSCALEP;
            }
}

// -------- BN stats (R9-proven) ------------------------------------------------
__global__ __launch_bounds__(256) void bn_part(int which, int chbase)
{
    const float* Y = which ? g_P : g_Y;
    int c = blockIdx.x, sp = blockIdx.y;
    const float* p = Y + (size_t)c * MM + sp * 4096;
    int t = threadIdx.x;
    double s = 0.0, ss = 0.0;
#pragma unroll
    for (int i = 0; i < 4; i++) {
        float4 v = *(const float4*)&p[i * 1024 + t * 4];
        s  += ((double)v.x + (double)v.y) + ((double)v.z + (double)v.w);
        ss += ((double)v.x * v.x + (double)v.y * v.y) + ((double)v.z * v.z + (double)v.w * v.w);
    }
#pragma unroll
    for (int o = 16; o > 0; o >>= 1) {
        s  += __shfl_down_sync(0xffffffffu, s,  o);
        ss += __shfl_down_sync(0xffffffffu, ss, o);
    }
    __shared__ double sh[8][2];
    int wp = t >> 5;
    if ((t & 31) == 0) { sh[wp][0] = s; sh[wp][1] = ss; }
    __syncthreads();
    if (t == 0) {
        double S = 0.0, SS = 0.0;
#pragma unroll
        for (int i = 0; i < 8; i++) { S += sh[i][0]; SS += sh[i][1]; }
        g_part[chbase + c][sp][0] = S;
        g_part[chbase + c][sp][1] = SS;
    }
}

__global__ __launch_bounds__(256) void bn_final(int partbase, int outbase, int which,
    const float* __restrict__ gamma, const float* __restrict__ beta)
{
    int c = blockIdx.x * 256 + threadIdx.x;
    double s = 0.0, ss = 0.0;
#pragma unroll
    for (int i = 0; i < 8; i++) { s += g_part[partbase + c][i][0]; ss += g_part[partbase + c][i][1]; }
    double mean = s * (1.0 / (double)MM);
    double var  = ss * (1.0 / (double)MM) - mean * mean;
    double inv  = 1.0 / sqrt(var + 1e-5);
    double g    = (double)gamma[c];
    float* sc = which ? g_scale2 : g_scale;
    float* sf = which ? g_shift2 : g_shift;
    sc[outbase + c] = (float)(g * inv);
    sf[outbase + c] = (float)((double)beta[c] - mean * g * inv);
}

// -------- LIF kernels (exact path, R9-proven) ----------------------------------
__global__ __launch_bounds__(256) void lif_qkv()
{
    int ch = blockIdx.x, b = blockIdx.y;
    float sc = g_scale[ch], sf = g_shift[ch];
    size_t base = (size_t)ch * MM + (size_t)b * 1024;
    for (int n = threadIdx.x; n < 1024; n += 256) {
        float v = 0.f;
#pragma unroll
        for (int t = 0; t < 4; t++) {
            size_t idx = base + (size_t)t * 8192 + n;
            float xv = g_Y[idx] * sc + sf;
            v = v + (xv - v) * 0.5f;
            bool s = (v >= 1.0f);
            g_S[idx] = s ? 1.f : 0.f;
            if (s) v = 0.f;
        }
    }
}

__global__ __launch_bounds__(256) void lif_attn()
{
    int ch = blockIdx.x, b = blockIdx.y;
    size_t base = (size_t)ch * MM + (size_t)b * 1024;
    for (int n = threadIdx.x; n < 1024; n += 256) {
        float v = 0.f;
#pragma unroll
        for (int t = 0; t < 4; t++) {
            size_t idx = base + (size_t)t * 8192 + n;
            float xv = g_A[idx];
            v = v + (xv - v) * 0.5f;
            bool s = (v >= 0.5f);
            g_Sa[idx] = s ? 1.f : 0.f;
            if (s) v = 0.f;
        }
    }
}

// -------- attention (exact integer arithmetic, R9-proven) -----------------------
__global__ __launch_bounds__(256) void kv_kernel()
{
    __shared__ float Ks[64][65];
    __shared__ float Vs[64][65];
    int g = blockIdx.x, tb = g >> 3, h = g & 7;
    int tid = threadIdx.x, tx = tid & 15, ty = tid >> 4;
    size_t kbase = (size_t)(512  + h * 64) * MM + (size_t)tb * 1024;
    size_t vbase = (size_t)(1024 + h * 64) * MM + (size_t)tb * 1024;
    float acc[4][4];
#pragma unroll
    for (int i = 0; i < 4; i++)
#pragma unroll
        for (int j = 0; j < 4; j++) acc[i][j] = 0.f;

    for (int n0 = 0; n0 < 1024; n0 += 64) {
        for (int i = tid; i < 1024; i += 256) {
            int d = i >> 4, c4 = (i & 15) << 2;
            float4 kk = *(const float4*)&g_S[kbase + (size_t)d * MM + n0 + c4];
            Ks[d][c4+0]=kk.x; Ks[d][c4+1]=kk.y; Ks[d][c4+2]=kk.z; Ks[d][c4+3]=kk.w;
            float4 vv = *(const float4*)&g_S[vbase + (size_t)d * MM + n0 + c4];
            Vs[d][c4+0]=vv.x; Vs[d][c4+1]=vv.y; Vs[d][c4+2]=vv.z; Vs[d][c4+3]=vv.w;
        }
        __syncthreads();
#pragma unroll
        for (int j = 0; j < 64; j++) {
            float kr[4], vr[4];
#pragma unroll
            for (int i = 0; i < 4; i++) kr[i] = Ks[ty*4+i][j];
#pragma unroll
            for (int i = 0; i < 4; i++) vr[i] = Vs[tx*4+i][j];
#pragma unroll
            for (int i = 0; i < 4; i++)
#pragma unroll
                for (int jj = 0; jj < 4; jj++)
                    acc[i][jj] = fmaf(kr[i], vr[jj], acc[i][jj]);
        }
        __syncthreads();
    }
#pragma unroll
    for (int i = 0; i < 4; i++)
#pragma unroll
        for (int j = 0; j < 4; j++)
            g_KV[(size_t)g*4096 + (ty*4+i)*64 + tx*4 + j] = acc[i][j];
}

__global__ __launch_bounds__(256) void attn_a()
{
    __shared__ float KVs[64][68];
    __shared__ float Qs [64][68];
    int n0 = blockIdx.x * 64, g = blockIdx.y;
    int tb = g >> 3, h = g & 7;
    int tid = threadIdx.x, tx = tid & 15, ty = tid >> 4;
    size_t qbase = (size_t)(h * 64) * MM + (size_t)tb * 1024 + n0;
    for (int i = tid; i < 1024; i += 256) {
        int d = i >> 4, c4 = (i & 15) << 2;
        *(float4*)&KVs[d][c4] = *(const float4*)&g_KV[(size_t)g*4096 + d*64 + c4];
        *(float4*)&Qs[d][c4]  = *(const float4*)&g_S[qbase + (size_t)d * MM + c4];
    }
    __syncthreads();
    float acc[4][4];
#pragma unroll
    for (int i = 0; i < 4; i++)
#pragma unroll
        for (int j = 0; j < 4; j++) acc[i][j] = 0.f;
#pragma unroll
    for (int d = 0; d < 64; d++) {
        float4 kv4 = *(const float4*)&KVs[d][ty*4];
        float4 q4  = *(const float4*)&Qs[d][tx*4];
        float kvv[4] = {kv4.x, kv4.y, kv4.z, kv4.w};
        float qv[4]  = {q4.x,  q4.y,  q4.z,  q4.w};
#pragma unroll
        for (int i = 0; i < 4; i++)
#pragma unroll
            for (int j = 0; j < 4; j++)
                acc[i][j] = fmaf(kvv[i], qv[j], acc[i][j]);
    }
#pragma unroll
    for (int i = 0; i < 4; i++) {
        int e = ty*4 + i;
        size_t base = (size_t)(h*64 + e) * MM + (size_t)tb * 1024 + n0 + tx*4;
        *(float4*)&g_A[base] = make_float4(0.125f*acc[i][0], 0.125f*acc[i][1],
                                           0.125f*acc[i][2], 0.125f*acc[i][3]);
    }
}

// -------- final LIF with flagging + transpose ----------------------------------
__global__ __launch_bounds__(256) void lif_final_flag(float* __restrict__ out)
{
    int c = blockIdx.x, b = blockIdx.y;
    float sc = g_scale2[c], sf = g_shift2[c];
    for (int n = threadIdx.x; n < 1024; n += 256) {
        float v = 0.f;
        bool close = false;
#pragma unroll
        for (int t = 0; t < 4; t++) {
            size_t idx = (size_t)c * MM + (size_t)(t*8 + b) * 1024 + n;
            float xv = g_P[idx] * sc + sf;
            v = v + (xv - v) * 0.5f;
            close |= (fabsf(v - 1.0f) < TAU);
            bool s = (v >= 1.0f);
            out[((size_t)(t*8 + b) * 512 + c) * 1024 + n] = s ? 1.f : 0.f;
            if (s) v = 0.f;
        }
        if (close) {
            int pos = atomicAdd(&g_cnt2, 1);
            if (pos < FLAG_CAP) g_list2[pos] = c * 8192 + b * 1024 + n;
        }
    }
}

// -------- fixup2: exact sequential-k chain for flagged output columns -----------
__global__ __launch_bounds__(256) void fixup2(const float* __restrict__ pw,
                                              float* __restrict__ out)
{
    int cnt = g_cnt2; if (cnt > FLAG_CAP) cnt = FLAG_CAP;
    for (int i = blockIdx.x * 256 + threadIdx.x; i < cnt; i += gridDim.x * 256) {
        int enc = g_list2[i];
        int c_out = enc >> 13;
        int bn = enc & 8191;
        int b = bn >> 10, n = bn & 1023;
        const float* w = pw + (size_t)c_out * 512;
        float sc = g_scale2[c_out], sf = g_shift2[c_out];
        float v = 0.f;
        for (int t = 0; t < 4; t++) {
            int m = t * 8192 + bn;
            float acc = 0.f;
            for (int c = 0; c < 512; c++)
                acc = fmaf(w[c], g_Sa[(size_t)c * MM + m], acc);
            float xv = acc * sc + sf;
            v = v + (xv - v) * 0.5f;
            bool s = (v >= 1.0f);
            out[((size_t)(t*8 + b) * 512 + c_out) * 1024 + n] = s ? 1.f : 0.f;
            if (s) v = 0.f;
        }
    }
}

// ---------------------------------------------------------------------------
extern "C" void kernel_launch(void* const* d_in, const int* in_sizes, int n_in,
                              void* d_out, int out_size)
{
    const float* x   = (const float*)d_in[0];
    const float* q_w = (const float*)d_in[1];
    const float* q_g = (const float*)d_in[2];
    const float* q_b = (const float*)d_in[3];
    const float* k_w = (const float*)d_in[4];
    const float* k_g = (const float*)d_in[5];
    const float* k_b = (const float*)d_in[6];
    const float* v_w = (const float*)d_in[7];
    const float* v_g = (const float*)d_in[8];
    const float* v_b = (const float*)d_in[9];
    const float* p_w = (const float*)d_in[10];
    // d_in[11] = proj_b: zeros in this dataset (cancels in training-mode BN anyway).
    const float* p_g = (const float*)d_in[12];
    const float* p_b = (const float*)d_in[13];
    float* out = (float*)d_out;

    zero_counters<<<1, 1>>>();
    prep_w_proj<<<4, 256>>>(p_w);

    // 1) QKV GEMM: exact scalar (bit-proven)
    gemm_qkv<<<dim3(MM/128, O3/128), 256>>>(q_w, k_w, v_w, x);
    bn_part<<<dim3(O3, 8), 256>>>(0, 0);
    bn_final<<<2, 256>>>(0,    0,    0, q_g, q_b);
    bn_final<<<2, 256>>>(512,  512,  0, k_g, k_b);
    bn_final<<<2, 256>>>(1024, 1024, 0, v_g, v_b);
    lif_qkv<<<dim3(O3, 8), 256>>>();

    // 2) attention (exact integers)
    kv_kernel<<<256, 256>>>();
    attn_a<<<dim3(16, 256), 256>>>();
    lif_attn<<<dim3(CC, 8), 256>>>();

    // 3) proj on tensor cores + near-threshold exact fixup
    pack_spike<<<dim3(256, 8), 128>>>();
    gemm_proj_tc<<<dim3(4, 256), 256>>>();
    bn_part<<<dim3(CC, 8), 256>>>(1, 1536);
    bn_final<<<2, 256>>>(1536, 0, 1, p_g, p_b);
    lif_final_flag<<<dim3(CC, 8), 256>>>(out);
    fixup2<<<512, 256>>>(p_w, out);
}

// round 14
// speedup vs baseline: 1.4423x; 1.4423x over previous
#include <cuda_runtime.h>
#include <math.h>

// Problem constants: T=4, B=8, N=1024, C=512, NH=8, D=64, TB=32, M=TB*N=32768
#define MM 32768
#define O3 1536
#define CC 512

// ---------------- scratch (static __device__, no allocation) ----------------
__device__ float g_Y [(size_t)O3 * MM];   // qkv pre-activations   [o][m]
__device__ float g_S [(size_t)O3 * MM];   // qkv spikes            [o][m]
__device__ float g_KV[256 * 64 * 64];     // kv per (t,b,h)        [g][d][e]
__device__ float g_A [(size_t)CC * MM];   // attention pre-LIF     [c][m]
__device__ float g_Sa[(size_t)CC * MM];   // attention spikes      [c][m]
__device__ float g_P [(size_t)CC * MM];   // proj pre-activations  [c][m]
__device__ float g_scale [O3], g_shift [O3];
__device__ float g_scale2[CC], g_shift2[CC];
__device__ double g_part[2048][8][2];     // BN partial sums [ch][slice][{s,ss}]

// ---------------- GEMM1: g_Y[o][m] = sum_c W[o][c] * X[m][c] ----------------
// Bit-exact vs reference: per output, k accumulated sequentially 0..511 via fmaf.
__global__ __launch_bounds__(256) void gemm_qkv(
    const float* __restrict__ Wq, const float* __restrict__ Wk,
    const float* __restrict__ Wv, const float* __restrict__ X)
{
    __shared__ float As[16][132];
    __shared__ float Bs[16][132];
    int m0 = blockIdx.x * 128;
    int o0 = blockIdx.y * 128;
    const float* W = Wq; int ob = o0;
    if (o0 >= 1024)      { W = Wv; ob = o0 - 1024; }
    else if (o0 >= 512)  { W = Wk; ob = o0 - 512;  }

    int tid = threadIdx.x;
    int tx = tid & 15, ty = tid >> 4;
    int lr = tid >> 2;            // 0..63
    int lk = (tid & 3) << 2;      // 0,4,8,12

    float acc[8][8];
#pragma unroll
    for (int i = 0; i < 8; i++)
#pragma unroll
        for (int j = 0; j < 8; j++) acc[i][j] = 0.f;

    for (int k0 = 0; k0 < 512; k0 += 16) {
#pragma unroll
        for (int rr = 0; rr < 2; rr++) {
            int r = lr + rr * 64;
            float4 a = *(const float4*)&W[(size_t)(ob + r) * 512 + k0 + lk];
            As[lk+0][r] = a.x; As[lk+1][r] = a.y; As[lk+2][r] = a.z; As[lk+3][r] = a.w;
            float4 b = *(const float4*)&X[(size_t)(m0 + r) * 512 + k0 + lk];
            Bs[lk+0][r] = b.x; Bs[lk+1][r] = b.y; Bs[lk+2][r] = b.z; Bs[lk+3][r] = b.w;
        }
        __syncthreads();
#pragma unroll
        for (int kk = 0; kk < 16; kk++) {
            float ar[8], br[8];
            *(float4*)&ar[0] = *(const float4*)&As[kk][ty*8];
            *(float4*)&ar[4] = *(const float4*)&As[kk][ty*8+4];
            *(float4*)&br[0] = *(const float4*)&Bs[kk][tx*8];
            *(float4*)&br[4] = *(const float4*)&Bs[kk][tx*8+4];
#pragma unroll
            for (int i = 0; i < 8; i++)
#pragma unroll
                for (int j = 0; j < 8; j++)
                    acc[i][j] = fmaf(ar[i], br[j], acc[i][j]);
        }
        __syncthreads();
    }
#pragma unroll
    for (int i = 0; i < 8; i++) {
        size_t row = (size_t)(o0 + ty*8 + i) * MM + m0 + tx*8;
        *(float4*)&g_Y[row]   = make_float4(acc[i][0], acc[i][1], acc[i][2], acc[i][3]);
        *(float4*)&g_Y[row+4] = make_float4(acc[i][4], acc[i][5], acc[i][6], acc[i][7]);
    }
}

// ---------------- GEMM2: g_P[o][m] = sum_c W[o][c] * g_Sa[c][m] -------------
__global__ __launch_bounds__(256) void gemm_proj(const float* __restrict__ W)
{
    __shared__ float As[16][132];
    __shared__ float Bs[16][132];
    int m0 = blockIdx.x * 128;
    int o0 = blockIdx.y * 128;
    int tid = threadIdx.x;
    int tx = tid & 15, ty = tid >> 4;
    int lr = tid >> 2;
    int lk = (tid & 3) << 2;
    int lc = tid >> 5;            // 0..7
    int lm = (tid & 31) << 2;     // 0..124

    float acc[8][8];
#pragma unroll
    for (int i = 0; i < 8; i++)
#pragma unroll
        for (int j = 0; j < 8; j++) acc[i][j] = 0.f;

    for (int k0 = 0; k0 < 512; k0 += 16) {
#pragma unroll
        for (int rr = 0; rr < 2; rr++) {
            int r = lr + rr * 64;
            float4 a = *(const float4*)&W[(size_t)(o0 + r) * 512 + k0 + lk];
            As[lk+0][r] = a.x; As[lk+1][r] = a.y; As[lk+2][r] = a.z; As[lk+3][r] = a.w;
        }
#pragma unroll
        for (int rr = 0; rr < 2; rr++) {
            int c = lc + rr * 8;
            float4 b = *(const float4*)&g_Sa[(size_t)(k0 + c) * MM + m0 + lm];
            *(float4*)&Bs[c][lm] = b;
        }
        __syncthreads();
#pragma unroll
        for (int kk = 0; kk < 16; kk++) {
            float ar[8], br[8];
            *(float4*)&ar[0] = *(const float4*)&As[kk][ty*8];
            *(float4*)&ar[4] = *(const float4*)&As[kk][ty*8+4];
            *(float4*)&br[0] = *(const float4*)&Bs[kk][tx*8];
            *(float4*)&br[4] = *(const float4*)&Bs[kk][tx*8+4];
#pragma unroll
            for (int i = 0; i < 8; i++)
#pragma unroll
                for (int j = 0; j < 8; j++)
                    acc[i][j] = fmaf(ar[i], br[j], acc[i][j]);
        }
        __syncthreads();
    }
#pragma unroll
    for (int i = 0; i < 8; i++) {
        size_t row = (size_t)(o0 + ty*8 + i) * MM + m0 + tx*8;
        *(float4*)&g_P[row]   = make_float4(acc[i][0], acc[i][1], acc[i][2], acc[i][3]);
        *(float4*)&g_P[row+4] = make_float4(acc[i][4], acc[i][5], acc[i][6], acc[i][7]);
    }
}

// -------- Neumaier compensated fp32 helpers -----------------------------------
__device__ __forceinline__ void neum_add(float& s, float& c, float x) {
    float t = s + x;
    float e = (fabsf(s) >= fabsf(x)) ? ((s - t) + x) : ((x - t) + s);
    c += e; s = t;
}
__device__ __forceinline__ void neum_merge(float& s, float& c, float s2, float c2) {
    float t = s + s2;
    float e = (fabsf(s) >= fabsf(s2)) ? ((s - t) + s2) : ((s2 - t) + s);
    c = c + c2 + e; s = t;
}

// -------- BN stats stage A: fp32 Neumaier sums (fp64 pipe eliminated) ---------
// Each block: one (channel, 1/8-slice) of 4096 values -> (sum, sumsq) partial.
__global__ __launch_bounds__(256) void bn_part(int which, int chbase)
{
    const float* Y = which ? g_P : g_Y;
    int c  = blockIdx.x;
    int sp = blockIdx.y;
    const float* p = Y + (size_t)c * MM + sp * 4096;
    int t = threadIdx.x;
    float s = 0.f, cs = 0.f, ss = 0.f, css = 0.f;
#pragma unroll
    for (int i = 0; i < 4; i++) {
        float4 v = *(const float4*)&p[i*1024 + t*4];
        neum_add(s, cs, v.x); neum_add(ss, css, v.x * v.x);
        neum_add(s, cs, v.y); neum_add(ss, css, v.y * v.y);
        neum_add(s, cs, v.z); neum_add(ss, css, v.z * v.z);
        neum_add(s, cs, v.w); neum_add(ss, css, v.w * v.w);
    }
#pragma unroll
    for (int o = 16; o > 0; o >>= 1) {
        float s2  = __shfl_down_sync(0xffffffffu, s,  o);
        float c2  = __shfl_down_sync(0xffffffffu, cs, o);
        neum_merge(s, cs, s2, c2);
        float t2  = __shfl_down_sync(0xffffffffu, ss,  o);
        float d2  = __shfl_down_sync(0xffffffffu, css, o);
        neum_merge(ss, css, t2, d2);
    }
    __shared__ float sh[8][4];
    int w = t >> 5;
    if ((t & 31) == 0) { sh[w][0] = s; sh[w][1] = cs; sh[w][2] = ss; sh[w][3] = css; }
    __syncthreads();
    if (t == 0) {
        double S = 0.0, SS = 0.0;
#pragma unroll
        for (int i = 0; i < 8; i++) {
            S  += (double)sh[i][0] + (double)sh[i][1];
            SS += (double)sh[i][2] + (double)sh[i][3];
        }
        g_part[chbase + c][sp][0] = S;
        g_part[chbase + c][sp][1] = SS;
    }
}

// -------- BN stats stage B: finalize 512 channels -> scale/shift --------------
__global__ __launch_bounds__(256) void bn_final(int partbase, int outbase, int which,
    const float* __restrict__ gamma, const float* __restrict__ beta)
{
    int c = blockIdx.x * 256 + threadIdx.x;   // 0..511
    double s = 0.0, ss = 0.0;
#pragma unroll
    for (int i = 0; i < 8; i++) {
        s  += g_part[partbase + c][i][0];
        ss += g_part[partbase + c][i][1];
    }
    double mean = s * (1.0 / (double)MM);
    double var  = ss * (1.0 / (double)MM) - mean * mean;
    double inv  = 1.0 / sqrt(var + 1e-5);
    double g    = (double)gamma[c];
    float* sc = which ? g_scale2 : g_scale;
    float* sf = which ? g_shift2 : g_shift;
    sc[outbase + c] = (float)(g * inv);
    sf[outbase + c] = (float)((double)beta[c] - mean * g * inv);
}

// -------- LIF over T (tau=2 -> *0.5, hard reset), qkv: vth=1.0 ----------------
__global__ __launch_bounds__(256) void lif_qkv()
{
    int ch = blockIdx.x;            // 0..1535
    int b  = blockIdx.y;            // 0..7
    float sc = g_scale[ch], sf = g_shift[ch];
    size_t base = (size_t)ch * MM + (size_t)b * 1024;
    for (int n = threadIdx.x; n < 1024; n += 256) {
        float v = 0.f;
#pragma unroll
        for (int t = 0; t < 4; t++) {
            size_t idx = base + (size_t)t * 8192 + n;
            float xv = g_Y[idx] * sc + sf;
            v = v + (xv - v) * 0.5f;
            bool s = (v >= 1.0f);
            g_S[idx] = s ? 1.f : 0.f;
            if (s) v = 0.f;
        }
    }
}

// -------- attn LIF: vth=0.5, no BN --------
__global__ __launch_bounds__(256) void lif_attn()
{
    int ch = blockIdx.x;            // 0..511
    int b  = blockIdx.y;
    size_t base = (size_t)ch * MM + (size_t)b * 1024;
    for (int n = threadIdx.x; n < 1024; n += 256) {
        float v = 0.f;
#pragma unroll
        for (int t = 0; t < 4; t++) {
            size_t idx = base + (size_t)t * 8192 + n;
            float xv = g_A[idx];
            v = v + (xv - v) * 0.5f;
            bool s = (v >= 0.5f);
            g_Sa[idx] = s ? 1.f : 0.f;
            if (s) v = 0.f;
        }
    }
}

// -------- kv[g][d][e] = sum_n K[d][n] * V[e][n], g=(tb,h), N=1024 -------------
__global__ __launch_bounds__(256) void kv_kernel()
{
    __shared__ float Ks[64][65];
    __shared__ float Vs[64][65];
    int g  = blockIdx.x;            // tb*8 + h
    int tb = g >> 3, h = g & 7;
    int tid = threadIdx.x;
    int tx = tid & 15, ty = tid >> 4;
    size_t kbase = (size_t)(512  + h*64) * MM + (size_t)tb * 1024;
    size_t vbase = (size_t)(1024 + h*64) * MM + (size_t)tb * 1024;
    float acc[4][4];
#pragma unroll
    for (int i = 0; i < 4; i++)
#pragma unroll
        for (int j = 0; j < 4; j++) acc[i][j] = 0.f;

    for (int n0 = 0; n0 < 1024; n0 += 64) {
        for (int i = tid; i < 1024; i += 256) {
            int d = i >> 4, c4 = (i & 15) << 2;
            float4 kk = *(const float4*)&g_S[kbase + (size_t)d * MM + n0 + c4];
            Ks[d][c4+0]=kk.x; Ks[d][c4+1]=kk.y; Ks[d][c4+2]=kk.z; Ks[d][c4+3]=kk.w;
            float4 vv = *(const float4*)&g_S[vbase + (size_t)d * MM + n0 + c4];
            Vs[d][c4+0]=vv.x; Vs[d][c4+1]=vv.y; Vs[d][c4+2]=vv.z; Vs[d][c4+3]=vv.w;
        }
        __syncthreads();
#pragma unroll
        for (int j = 0; j < 64; j++) {
            float kr[4], vr[4];
#pragma unroll
            for (int i = 0; i < 4; i++) kr[i] = Ks[ty*4+i][j];
#pragma unroll
            for (int i = 0; i < 4; i++) vr[i] = Vs[tx*4+i][j];
#pragma unroll
            for (int i = 0; i < 4; i++)
#pragma unroll
                for (int jj = 0; jj < 4; jj++)
                    acc[i][jj] = fmaf(kr[i], vr[jj], acc[i][jj]);
        }
        __syncthreads();
    }
#pragma unroll
    for (int i = 0; i < 4; i++)
#pragma unroll
        for (int j = 0; j < 4; j++)
            g_KV[(size_t)g*4096 + (ty*4+i)*64 + tx*4 + j] = acc[i][j];
}

// -------- a[c=h*64+e][m] = 0.125 * sum_d kv[d][e] * Q[d][n] -------------------
__global__ __launch_bounds__(256) void attn_a()
{
    __shared__ float KVs[64][68];
    __shared__ float Qs [64][68];
    int n0 = blockIdx.x * 64;       // 16 tiles of n
    int g  = blockIdx.y;            // 256 groups
    int tb = g >> 3, h = g & 7;
    int tid = threadIdx.x;
    int tx = tid & 15, ty = tid >> 4;
    size_t qbase = (size_t)(h*64) * MM + (size_t)tb * 1024 + n0;
    for (int i = tid; i < 1024; i += 256) {
        int d = i >> 4, c4 = (i & 15) << 2;
        *(float4*)&KVs[d][c4] = *(const float4*)&g_KV[(size_t)g*4096 + d*64 + c4];
        *(float4*)&Qs[d][c4]  = *(const float4*)&g_S[qbase + (size_t)d * MM + c4];
    }
    __syncthreads();
    float acc[4][4];
#pragma unroll
    for (int i = 0; i < 4; i++)
#pragma unroll
        for (int j = 0; j < 4; j++) acc[i][j] = 0.f;
#pragma unroll
    for (int d = 0; d < 64; d++) {
        float4 kv4 = *(const float4*)&KVs[d][ty*4];   // e = ty*4..+3
        float4 q4  = *(const float4*)&Qs[d][tx*4];    // n = tx*4..+3
        float kvv[4] = {kv4.x, kv4.y, kv4.z, kv4.w};
        float qv[4]  = {q4.x,  q4.y,  q4.z,  q4.w};
#pragma unroll
        for (int i = 0; i < 4; i++)
#pragma unroll
            for (int j = 0; j < 4; j++)
                acc[i][j] = fmaf(kvv[i], qv[j], acc[i][j]);
    }
#pragma unroll
    for (int i = 0; i < 4; i++) {
        int e = ty*4 + i;
        size_t base = (size_t)(h*64 + e) * MM + (size_t)tb * 1024 + n0 + tx*4;
        *(float4*)&g_A[base] = make_float4(0.125f*acc[i][0], 0.125f*acc[i][1],
                                           0.125f*acc[i][2], 0.125f*acc[i][3]);
    }
}

// -------- final LIF (vth=1.0) + transpose to output [t][b][c][n] --------------
__global__ __launch_bounds__(256) void lif_final(float* __restrict__ out)
{
    int c = blockIdx.x;             // 0..511
    int b = blockIdx.y;             // 0..7
    float sc = g_scale2[c], sf = g_shift2[c];
    for (int n = threadIdx.x; n < 1024; n += 256) {
        float v = 0.f;
#pragma unroll
        for (int t = 0; t < 4; t++) {
            size_t idx = (size_t)c * MM + (size_t)(t*8 + b) * 1024 + n;
            float xv = g_P[idx] * sc + sf;
            v = v + (xv - v) * 0.5f;
            bool s = (v >= 1.0f);
            out[((size_t)(t*8 + b) * 512 + c) * 1024 + n] = s ? 1.f : 0.f;
            if (s) v = 0.f;
        }
    }
}

// ---------------------------------------------------------------------------
extern "C" void kernel_launch(void* const* d_in, const int* in_sizes, int n_in,
                              void* d_out, int out_size)
{
    const float* x   = (const float*)d_in[0];
    const float* q_w = (const float*)d_in[1];
    const float* q_g = (const float*)d_in[2];
    const float* q_b = (const float*)d_in[3];
    const float* k_w = (const float*)d_in[4];
    const float* k_g = (const float*)d_in[5];
    const float* k_b = (const float*)d_in[6];
    const float* v_w = (const float*)d_in[7];
    const float* v_g = (const float*)d_in[8];
    const float* v_b = (const float*)d_in[9];
    const float* p_w = (const float*)d_in[10];
    // d_in[11] = proj_b: added before training-mode BN -> cancels exactly.
    const float* p_g = (const float*)d_in[12];
    const float* p_b = (const float*)d_in[13];
    float* out = (float*)d_out;

    // 1) fused QKV GEMM (bit-exact sequential-k fp32 fma)
    gemm_qkv<<<dim3(MM/128, O3/128), 256>>>(q_w, k_w, v_w, x);
    // 2) BN stats: fp32 Neumaier partials (fp64 pipe eliminated) + finalize
    bn_part<<<dim3(O3, 8), 256>>>(0, 0);
    bn_final<<<2, 256>>>(0,    0,    0, q_g, q_b);
    bn_final<<<2, 256>>>(512,  512,  0, k_g, k_b);
    bn_final<<<2, 256>>>(1024, 1024, 0, v_g, v_b);
    // 3) LIF -> binary spikes (vth=1.0)
    lif_qkv<<<dim3(O3, 8), 256>>>();
    // 4) kv = K^T V per (t,b,h)  (exact: integer-valued sums)
    kv_kernel<<<256, 256>>>();
    // 5) a = Q kv * 0.125 (exact)
    attn_a<<<dim3(16, 256), 256>>>();
    // 6) attn LIF (vth=0.5)
    lif_attn<<<dim3(CC, 8), 256>>>();
    // 7) proj GEMM (bit-exact sequential-k fp32 fma)
    gemm_proj<<<dim3(MM/128, CC/128), 256>>>(p_w);
    // 8) proj BN stats
    bn_part<<<dim3(CC, 8), 256>>>(1, 1536);
    bn_final<<<2, 256>>>(1536, 0, 1, p_g, p_b);
    // 9) final LIF + transpose to [T,B,C,H,W]
    lif_final<<<dim3(CC, 8), 256>>>(out);
}